// round 7
// baseline (speedup 1.0000x reference)
#include <cuda_runtime.h>
#include <cuda_bf16.h>
#include <cstdint>

#define BT_   8192
#define IN_   4096
#define OUT_  4096
#define R_    64
#define T_    8

// ---------------- device scratch ----------------
__device__ float          g_W1[T_ * R_ * R_];
__device__ __nv_bfloat16  g_Bthi[T_ * R_ * IN_];   // Bt = in_core@W1 : [t][n][k]
__device__ __nv_bfloat16  g_Btlo[T_ * R_ * IN_];
__device__ __nv_bfloat16  g_ochi[OUT_ * R_];       // out_core [n][k]
__device__ __nv_bfloat16  g_oclo[OUT_ * R_];
__device__ float          g_vpart[2][BT_ * R_];    // split-K partials of v

typedef unsigned long long u64;

// ---------- packed f32x2 ----------
__device__ __forceinline__ u64 pk2(float lo, float hi) {
    u64 r; asm("mov.b64 %0, {%1, %2};" : "=l"(r) : "f"(lo), "f"(hi)); return r;
}
__device__ __forceinline__ void upk2(u64 v, float& lo, float& hi) {
    asm("mov.b64 {%0, %1}, %2;" : "=f"(lo), "=f"(hi) : "l"(v));
}
__device__ __forceinline__ u64 ffma2(u64 a, u64 b, u64 c) {
    u64 d; asm("fma.rn.f32x2 %0, %1, %2, %3;" : "=l"(d) : "l"(a), "l"(b), "l"(c)); return d;
}

// ---------- fp32 -> bf16 hi/lo split ----------
__device__ __forceinline__ void split4(float4 v, uint32_t& h01, uint32_t& h23,
                                       uint32_t& l01, uint32_t& l23) {
    __nv_bfloat162 h0 = __floats2bfloat162_rn(v.x, v.y);
    __nv_bfloat162 h1 = __floats2bfloat162_rn(v.z, v.w);
    float rx = v.x - __bfloat162float(h0.x);
    float ry = v.y - __bfloat162float(h0.y);
    float rz = v.z - __bfloat162float(h1.x);
    float rw = v.w - __bfloat162float(h1.y);
    __nv_bfloat162 l0 = __floats2bfloat162_rn(rx, ry);
    __nv_bfloat162 l1 = __floats2bfloat162_rn(rz, rw);
    h01 = *(uint32_t*)&h0; h23 = *(uint32_t*)&h1;
    l01 = *(uint32_t*)&l0; l23 = *(uint32_t*)&l1;
}

// ---------- tensor-core primitives (base-ISA, sm_103-safe) ----------
__device__ __forceinline__ void mma16816(float* c, uint32_t a0, uint32_t a1,
                                         uint32_t a2, uint32_t a3,
                                         uint32_t b0, uint32_t b1) {
    asm volatile(
        "mma.sync.aligned.m16n8k16.row.col.f32.bf16.bf16.f32 "
        "{%0,%1,%2,%3}, {%4,%5,%6,%7}, {%8,%9}, {%0,%1,%2,%3};"
        : "+f"(c[0]), "+f"(c[1]), "+f"(c[2]), "+f"(c[3])
        : "r"(a0), "r"(a1), "r"(a2), "r"(a3), "r"(b0), "r"(b1));
}
__device__ __forceinline__ void ldsm4(uint32_t* r, uint32_t saddr) {
    asm volatile("ldmatrix.sync.aligned.m8n8.x4.shared.b16 {%0,%1,%2,%3}, [%4];"
                 : "=r"(r[0]), "=r"(r[1]), "=r"(r[2]), "=r"(r[3]) : "r"(saddr));
}
__device__ __forceinline__ void cpa16(uint32_t dst, const void* src) {
    asm volatile("cp.async.cg.shared.global [%0], [%1], 16;" :: "r"(dst), "l"(src));
}
#define CP_COMMIT() asm volatile("cp.async.commit_group;" ::: "memory")
#define CP_WAIT0()  asm volatile("cp.async.wait_group 0;" ::: "memory")
#define CP_WAIT1()  asm volatile("cp.async.wait_group 1;" ::: "memory")

__device__ __forceinline__ uint32_t smem_u32(const void* p) {
    uint32_t a;
    asm("{ .reg .u64 t; cvta.to.shared.u64 t, %1; cvt.u32.u64 %0, t; }" : "=r"(a) : "l"(p));
    return a;
}

// row stride in all smem tile matrices: 144 bytes (36 words) -> LDSM conflict-free
#define RSTR 144

// ---------------------------------------------------------------------------
// k_pre1: out_core hi/lo split (bx<64) + W1 (bx in [64,192)).
// ---------------------------------------------------------------------------
__global__ __launch_bounds__(256) void k_pre1(const float* __restrict__ task,
                                              const float* __restrict__ tc,
                                              const float* __restrict__ out_core) {
    const int bx = blockIdx.x, tid = threadIdx.x;
    if (bx < 64) {
        const size_t base = (size_t)bx * 4096 + (size_t)tid * 16;
#pragma unroll
        for (int j = 0; j < 16; j += 4) {
            float4 v = *(const float4*)&out_core[base + j];
            uint32_t h01, h23, l01, l23;
            split4(v, h01, h23, l01, l23);
            *(uint32_t*)&g_ochi[base + j]     = h01;
            *(uint32_t*)&g_ochi[base + j + 2] = h23;
            *(uint32_t*)&g_oclo[base + j]     = l01;
            *(uint32_t*)&g_oclo[base + j + 2] = l23;
        }
    } else {
        const int idx = (bx - 64) * 256 + tid;
        const int t = idx >> 12, kl = idx & 4095;
        float a0 = 0, a1 = 0, a2 = 0, a3 = 0;
#pragma unroll
        for (int j = 0; j < 64; j += 4) {
            a0 += task[t * 64 + j + 0] * tc[(size_t)(j + 0) * 4096 + kl];
            a1 += task[t * 64 + j + 1] * tc[(size_t)(j + 1) * 4096 + kl];
            a2 += task[t * 64 + j + 2] * tc[(size_t)(j + 2) * 4096 + kl];
            a3 += task[t * 64 + j + 3] * tc[(size_t)(j + 3) * 4096 + kl];
        }
        g_W1[idx] = (a0 + a1) + (a2 + a3);
    }
}

// ---------------------------------------------------------------------------
// k_bt: Bt[t][k][n] = sum_j in_core[k][j] * W1[t][j][n], split to bf16 hi/lo,
// stored transposed as [t][n][k].  grid 128: t = bx>>4, kc = (bx&15)*256.
// ---------------------------------------------------------------------------
__global__ __launch_bounds__(256) void k_bt(const float* __restrict__ in_core) {
    __shared__ float W1s[4096];
    const int bx = blockIdx.x, tid = threadIdx.x;
    const int t = bx >> 4;
    const int row = (bx & 15) * 256 + tid;      // k index
    {
        const float4* src = (const float4*)(g_W1 + t * 4096);
        float4* dst = (float4*)W1s;
#pragma unroll
        for (int i = 0; i < 4; i++) dst[tid + i * 256] = src[tid + i * 256];
    }
    __syncthreads();

    u64 acc[32];
#pragma unroll
    for (int i = 0; i < 32; i++) acc[i] = 0ull;

    const float* icr = in_core + (size_t)row * 64;
#pragma unroll
    for (int jc = 0; jc < 4; jc++) {
        float4 a4[4];
#pragma unroll
        for (int q = 0; q < 4; q++) a4[q] = *(const float4*)(icr + jc * 16 + q * 4);
#pragma unroll
        for (int jj = 0; jj < 16; jj++) {
            const int j = jc * 16 + jj;
            float a = ((const float*)a4)[jj];
            u64 a2 = pk2(a, a);
#pragma unroll
            for (int i2 = 0; i2 < 16; i2++) {
                ulonglong2 w = *(const ulonglong2*)&W1s[j * 64 + i2 * 4];
                acc[2 * i2]     = ffma2(a2, w.x, acc[2 * i2]);
                acc[2 * i2 + 1] = ffma2(a2, w.y, acc[2 * i2 + 1]);
            }
        }
    }
    // split + transposed store: Bt[t][n][row]
#pragma unroll
    for (int i = 0; i < 32; i++) {
        float v0, v1;
        upk2(acc[i], v0, v1);
        __nv_bfloat16 h0 = __float2bfloat16(v0);
        __nv_bfloat16 l0 = __float2bfloat16(v0 - __bfloat162float(h0));
        __nv_bfloat16 h1 = __float2bfloat16(v1);
        __nv_bfloat16 l1 = __float2bfloat16(v1 - __bfloat162float(h1));
        const size_t b0 = ((size_t)t * 64 + 2 * i) * IN_ + row;
        const size_t b1 = ((size_t)t * 64 + 2 * i + 1) * IN_ + row;
        g_Bthi[b0] = h0; g_Btlo[b0] = l0;
        g_Bthi[b1] = h1; g_Btlo[b1] = l1;
    }
}

// ---------------------------------------------------------------------------
// k_gemm1: v_partial = x @ Bt[t]  (tile 64m x 64n, K-slice 2048 = 32 chunks
// of 64). 256 CTAs: mtile = bx>>1 (t = mtile&7, g = mtile>>3), kslice = bx&1.
// 3-stage cp.async pipeline for B (wait_group 1 => chunk ready a full chunk
// early); x LDG pipelined in registers, split+STS after compute.
// stage 36864B: AH@0 AL@9216 BH@18432 BL@27648;  3 stages = 110592B.
// ---------------------------------------------------------------------------
#define G1_STG  36864
#define G1_SMEM (3 * G1_STG)

__global__ __launch_bounds__(256, 2) void k_gemm1(const float* __restrict__ x) {
    extern __shared__ char sm[];
    const uint32_t sb = smem_u32(sm);
    const int tid = threadIdx.x, warp = tid >> 5, lane = tid & 31;
    const int gr = lane >> 2, p = lane & 3;
    const int bx = blockIdx.x;
    const int mtile = bx >> 1, ksl = bx & 1;
    const int t = mtile & 7, g = mtile >> 3;
    const int koff = ksl * 2048;

    // x loader mapping: 4 threads per row
    const int lrow = tid >> 2, lq = tid & 3;
    const float* xrp = x + (size_t)(t + 8 * (g * 64 + lrow)) * IN_ + koff;

    // B cp.async mapping
    const int bn = tid >> 2, bj = tid & 3;
    const __nv_bfloat16* bth = g_Bthi + ((size_t)t * 64 + bn) * IN_ + koff;
    const __nv_bfloat16* btl = g_Btlo + ((size_t)t * 64 + bn) * IN_ + koff;
    const uint32_t dB = sb + 18432 + bn * RSTR;

    // ldmatrix lane roles
    const int m0 = (warp >> 1) * 16, n0 = (warp & 1) * 32;
    const int lr = (lane & 7) + ((lane >> 3) & 1) * 8;
    const int lk = (lane >> 4) * 16;
    const uint32_t offA = (uint32_t)((m0 + lr) * RSTR + lk);
    const uint32_t offB = (uint32_t)((n0 + lr) * RSTR + lk);

    float acc[4][4];
#pragma unroll
    for (int i = 0; i < 4; i++) acc[i][0] = acc[i][1] = acc[i][2] = acc[i][3] = 0.f;

    float4 xv[4];

#define G1_BLOAD(st_, c_) do {                                                \
    const uint32_t d = dB + (st_) * G1_STG;                                   \
    cpa16(d + bj * 16,        bth + (c_) * 64 + bj * 8);                      \
    cpa16(d + (bj + 4) * 16,  bth + (c_) * 64 + (bj + 4) * 8);                \
    cpa16(d + 9216 + bj * 16,       btl + (c_) * 64 + bj * 8);                \
    cpa16(d + 9216 + (bj + 4) * 16, btl + (c_) * 64 + (bj + 4) * 8);          \
} while (0)

#define G1_XLDG(c_) do {                                                      \
    const float* srcx = xrp + (c_) * 64;                                      \
    _Pragma("unroll")                                                         \
    for (int seg = 0; seg < 4; seg++)                                         \
        xv[seg] = *(const float4*)(srcx + seg * 16 + lq * 4);                 \
} while (0)

#define G1_XSTS(st_) do {                                                     \
    char* ah = sm + (st_) * G1_STG + lrow * RSTR + lq * 8;                    \
    _Pragma("unroll")                                                         \
    for (int seg = 0; seg < 4; seg++) {                                       \
        uint32_t h01, h23, l01, l23;                                          \
        split4(xv[seg], h01, h23, l01, l23);                                  \
        *(uint2*)(ah + seg * 32)        = make_uint2(h01, h23);               \
        *(uint2*)(ah + 9216 + seg * 32) = make_uint2(l01, l23);               \
    }                                                                         \
} while (0)

    // prologue: B chunks 0,1 in flight; x chunk 0 stored, chunk 1 in regs
    G1_BLOAD(0, 0);
    CP_COMMIT();
    G1_BLOAD(1, 1);
    CP_COMMIT();
    G1_XLDG(0);
    G1_XSTS(0);
    G1_XLDG(1);

    for (int c = 0; c < 32; c++) {
        const int s = c - (c / 3) * 3;             // c % 3
        CP_WAIT1();                                // chunk c's B group done
        __syncthreads();
        if (c + 2 < 32) {
            const int s2 = (c + 2) - ((c + 2) / 3) * 3;
            G1_BLOAD(s2, c + 2);
            CP_COMMIT();
        }
        // compute chunk c from stage s
        const uint32_t st = sb + s * G1_STG;
#pragma unroll
        for (int ks = 0; ks < 4; ks++) {
            const uint32_t ka = ks * 32;
            uint32_t Ah[4], Al[4], B0[4], B1[4], L0[4], L1[4];
            ldsm4(Ah, st + offA + ka);
            ldsm4(B0, st + 18432 + offB + ka);
            ldsm4(B1, st + 18432 + 16 * RSTR + offB + ka);
            ldsm4(Al, st + 9216 + offA + ka);
            ldsm4(L0, st + 27648 + offB + ka);
            ldsm4(L1, st + 27648 + 16 * RSTR + offB + ka);
            // hi*hi
            mma16816(acc[0], Ah[0], Ah[1], Ah[2], Ah[3], B0[0], B0[2]);
            mma16816(acc[1], Ah[0], Ah[1], Ah[2], Ah[3], B0[1], B0[3]);
            mma16816(acc[2], Ah[0], Ah[1], Ah[2], Ah[3], B1[0], B1[2]);
            mma16816(acc[3], Ah[0], Ah[1], Ah[2], Ah[3], B1[1], B1[3]);
            // lo*hi
            mma16816(acc[0], Al[0], Al[1], Al[2], Al[3], B0[0], B0[2]);
            mma16816(acc[1], Al[0], Al[1], Al[2], Al[3], B0[1], B0[3]);
            mma16816(acc[2], Al[0], Al[1], Al[2], Al[3], B1[0], B1[2]);
            mma16816(acc[3], Al[0], Al[1], Al[2], Al[3], B1[1], B1[3]);
            // hi*lo
            mma16816(acc[0], Ah[0], Ah[1], Ah[2], Ah[3], L0[0], L0[2]);
            mma16816(acc[1], Ah[0], Ah[1], Ah[2], Ah[3], L0[1], L0[3]);
            mma16816(acc[2], Ah[0], Ah[1], Ah[2], Ah[3], L1[0], L1[2]);
            mma16816(acc[3], Ah[0], Ah[1], Ah[2], Ah[3], L1[1], L1[3]);
        }
        if (c + 1 < 32) {
            const int s1 = (c + 1) - ((c + 1) / 3) * 3;
            G1_XSTS(s1);                           // split+store after compute
        }
        if (c + 2 < 32) G1_XLDG(c + 2);            // LDG hidden under next iter
    }

    // store partials (deterministic plain stores)
    float* vp = g_vpart[ksl];
    const size_t r0 = (size_t)(t + 8 * (g * 64 + m0 + gr));
    const size_t r1 = r0 + 64;   // row + 8 in tile = +64 global
#pragma unroll
    for (int nt = 0; nt < 4; nt++) {
        const int col = n0 + nt * 8 + 2 * p;
        *(float2*)&vp[r0 * 64 + col] = make_float2(acc[nt][0], acc[nt][1]);
        *(float2*)&vp[r1 * 64 + col] = make_float2(acc[nt][2], acc[nt][3]);
    }
}

// ---------------------------------------------------------------------------
// k_gemm2: y = v @ out_core^T. Tile 128x128, K=64 one shot, warp tile 64x32.
// A built inline: vpart[0]+vpart[1] (fp32, L2-resident) summed + split in the
// loader while B arrives via cp.async.  2 CTAs/SM.
// smem: AH@0 AL@18432 BH@36864 BL@55296 (128 rows x 144B each) = 73728B.
// ---------------------------------------------------------------------------
#define G2_SMEM 73728

__global__ __launch_bounds__(256, 2) void k_gemm2(float* __restrict__ y) {
    extern __shared__ char sm[];
    const uint32_t sb = smem_u32(sm);
    const int tid = threadIdx.x, warp = tid >> 5, lane = tid & 31;
    const int gr = lane >> 2, p = lane & 3;
    const int n0b = blockIdx.x * 128, m0b = blockIdx.y * 128;

    {   // B tiles via cp.async (pre-split bf16)
        const int row = tid >> 1, q = (tid & 1) * 4;
        const uint32_t drow = sb + row * RSTR;
        const __nv_bfloat16* sbh = g_ochi + (size_t)(n0b + row) * 64;
        const __nv_bfloat16* sbl = g_oclo + (size_t)(n0b + row) * 64;
#pragma unroll
        for (int j = 0; j < 4; j++) {
            cpa16(drow + 36864 + (q + j) * 16, sbh + (q + j) * 8);
            cpa16(drow + 55296 + (q + j) * 16, sbl + (q + j) * 8);
        }
    }
    CP_COMMIT();
    {   // A tile: sum the two fp32 split-K partials, split to bf16 hi/lo
        const int row = tid >> 1, q = (tid & 1) * 8;   // float4 units
        const float4* p0 = (const float4*)(g_vpart[0] + (size_t)(m0b + row) * 64) + q;
        const float4* p1 = (const float4*)(g_vpart[1] + (size_t)(m0b + row) * 64) + q;
        char* da = sm + row * RSTR + q * 8;
#pragma unroll
        for (int j = 0; j < 8; j++) {
            float4 a = p0[j], b = p1[j];
            float4 s = make_float4(a.x + b.x, a.y + b.y, a.z + b.z, a.w + b.w);
            uint32_t h01, h23, l01, l23;
            split4(s, h01, h23, l01, l23);
            *(uint2*)(da + j * 8)         = make_uint2(h01, h23);
            *(uint2*)(da + 18432 + j * 8) = make_uint2(l01, l23);
        }
    }
    CP_WAIT0();
    __syncthreads();

    const int m0 = (warp >> 2) * 64, n0 = (warp & 3) * 32;
    const int lr = (lane & 7) + ((lane >> 3) & 1) * 8;
    const int lk = (lane >> 4) * 16;
    const uint32_t offA = (uint32_t)((m0 + lr) * RSTR + lk);
    const uint32_t offB = (uint32_t)((n0 + lr) * RSTR + lk);

    float acc[4][4][4];
#pragma unroll
    for (int mt = 0; mt < 4; mt++)
#pragma unroll
        for (int nt = 0; nt < 4; nt++)
            acc[mt][nt][0] = acc[mt][nt][1] = acc[mt][nt][2] = acc[mt][nt][3] = 0.f;

#pragma unroll
    for (int ks = 0; ks < 4; ks++) {
        const uint32_t ka = ks * 32;
        uint32_t Ah[4][4], Al[4][4], B0[4], B1[4], L0[4], L1[4];
#pragma unroll
        for (int mt = 0; mt < 4; mt++)
            ldsm4(Ah[mt], sb + offA + mt * 16 * RSTR + ka);
        ldsm4(B0, sb + 36864 + offB + ka);
        ldsm4(B1, sb + 36864 + 16 * RSTR + offB + ka);
        // hi*hi
#pragma unroll
        for (int mt = 0; mt < 4; mt++) {
            mma16816(acc[mt][0], Ah[mt][0], Ah[mt][1], Ah[mt][2], Ah[mt][3], B0[0], B0[2]);
            mma16816(acc[mt][1], Ah[mt][0], Ah[mt][1], Ah[mt][2], Ah[mt][3], B0[1], B0[3]);
            mma16816(acc[mt][2], Ah[mt][0], Ah[mt][1], Ah[mt][2], Ah[mt][3], B1[0], B1[2]);
            mma16816(acc[mt][3], Ah[mt][0], Ah[mt][1], Ah[mt][2], Ah[mt][3], B1[1], B1[3]);
        }
        // hi*lo
        ldsm4(L0, sb + 55296 + offB + ka);
        ldsm4(L1, sb + 55296 + 16 * RSTR + offB + ka);
#pragma unroll
        for (int mt = 0; mt < 4; mt++) {
            mma16816(acc[mt][0], Ah[mt][0], Ah[mt][1], Ah[mt][2], Ah[mt][3], L0[0], L0[2]);
            mma16816(acc[mt][1], Ah[mt][0], Ah[mt][1], Ah[mt][2], Ah[mt][3], L0[1], L0[3]);
            mma16816(acc[mt][2], Ah[mt][0], Ah[mt][1], Ah[mt][2], Ah[mt][3], L1[0], L1[2]);
            mma16816(acc[mt][3], Ah[mt][0], Ah[mt][1], Ah[mt][2], Ah[mt][3], L1[1], L1[3]);
        }
        // lo*hi
#pragma unroll
        for (int mt = 0; mt < 4; mt++)
            ldsm4(Al[mt], sb + 18432 + offA + mt * 16 * RSTR + ka);
#pragma unroll
        for (int mt = 0; mt < 4; mt++) {
            mma16816(acc[mt][0], Al[mt][0], Al[mt][1], Al[mt][2], Al[mt][3], B0[0], B0[2]);
            mma16816(acc[mt][1], Al[mt][0], Al[mt][1], Al[mt][2], Al[mt][3], B0[1], B0[3]);
            mma16816(acc[mt][2], Al[mt][0], Al[mt][1], Al[mt][2], Al[mt][3], B1[0], B1[2]);
            mma16816(acc[mt][3], Al[mt][0], Al[mt][1], Al[mt][2], Al[mt][3], B1[1], B1[3]);
        }
    }

#pragma unroll
    for (int mt = 0; mt < 4; mt++) {
#pragma unroll
        for (int nt = 0; nt < 4; nt++) {
            const int row = m0b + m0 + mt * 16 + gr;
            const int col = n0b + n0 + nt * 8 + 2 * p;
            *(float2*)&y[(size_t)row * OUT_ + col] =
                make_float2(acc[mt][nt][0], acc[mt][nt][1]);
            *(float2*)&y[(size_t)(row + 8) * OUT_ + col] =
                make_float2(acc[mt][nt][2], acc[mt][nt][3]);
        }
    }
}

// ---------------------------------------------------------------------------
extern "C" void kernel_launch(void* const* d_in, const int* in_sizes, int n_in,
                              void* d_out, int out_size) {
    const float* x        = (const float*)d_in[0];
    const float* tc       = (const float*)d_in[1];
    const float* task     = (const float*)d_in[2];
    const float* in_core  = (const float*)d_in[3];
    const float* out_core = (const float*)d_in[4];
    float* y = (float*)d_out;

    cudaFuncSetAttribute(k_gemm1, cudaFuncAttributeMaxDynamicSharedMemorySize, G1_SMEM);
    cudaFuncSetAttribute(k_gemm2, cudaFuncAttributeMaxDynamicSharedMemorySize, G2_SMEM);

    k_pre1<<<192, 256>>>(task, tc, out_core);
    k_bt<<<128, 256>>>(in_core);
    k_gemm1<<<256, 256, G1_SMEM>>>(x);
    k_gemm2<<<dim3(OUT_ / 128, BT_ / 128), 256, G2_SMEM>>>(y);
}